// round 14
// baseline (speedup 1.0000x reference)
#include <cuda_runtime.h>
#include <cstdint>

// ---------------------------------------------------------------------------
// SpikingSelfAttention: T=4, B=16, N=1024, D=512, H=8 (heads never mix).
//   1) g = x @ [Wq;Wk;Wv]^T          (65536 x 1536 x 512 fp32 GEMM)
//   2) LIF over time + ctx = cumsum_t(k*v), y = q*ctx   (elementwise)
//   3) out = y @ Wp^T + bp           (65536 x 512 x 512 fp32 GEMM)
//
// Numerics contract: per-lane IEEE fp32 FMA, k accumulated strictly
// sequentially (0..511) — measured bit-exact vs reference (rel_err = 0.0).
// Measured (R13): FFMA2 halves issue slots (71->42%) but fp32 datapath rate
// unchanged (fma 63.6%); bottleneck is datapath idle around the per-tile
// store/barrier phase. This version hoists the smem commit mid-loop.
// ---------------------------------------------------------------------------

#define T_STEPS 4
#define M_PER_T 16384            // B*N
#define ROWS    65536            // T*B*N
#define D_DIM   512
#define N_QKV   1536

// Scratch (allocation-guard-safe: __device__ globals)
__device__ float g_pre[(size_t)ROWS * N_QKV];   // QKV pre-activations, ld=1536
__device__ float g_y[(size_t)ROWS * D_DIM];     // y = q * context,     ld=512

#define BM 128
#define BN 128
#define BK 16

// Packed fp32x2 helpers (Blackwell sm_103a). Each f32x2 FMA = 2 independent
// IEEE fp32 FMAs — bit-identical per lane to scalar fmaf.
__device__ __forceinline__ void ffma2(unsigned long long& d,
                                      unsigned long long a,
                                      unsigned long long b,
                                      unsigned long long c) {
    asm("fma.rn.f32x2 %0, %1, %2, %3;" : "=l"(d) : "l"(a), "l"(b), "l"(c));
}
__device__ __forceinline__ unsigned long long splat2(float f) {
    unsigned long long d;
    asm("mov.b64 %0, {%1, %1};" : "=l"(d) : "f"(f));
    return d;
}
__device__ __forceinline__ void unpack2(float& lo, float& hi, unsigned long long v) {
    asm("mov.b64 {%0, %1}, %2;" : "=f"(lo), "=f"(hi) : "l"(v));
}

// out[i,j] = sum_k A[i,k] * B[j,k]   (A: M x K row-major, B: N x K row-major)
// If B1 != nullptr, column block selects among {B0,B1,B2} (512 cols each).
// Smem double-buffered; prefetched tile committed to smem MID-compute
// (after kk=7) so the post-compute path is FMAs -> BAR with STS retired.
__global__ __launch_bounds__(256) void sgemm_nt(
    const float* __restrict__ A, int lda,
    const float* __restrict__ B0, const float* __restrict__ B1,
    const float* __restrict__ B2,
    float* __restrict__ C, int ldc, int K,
    const float* __restrict__ bias)
{
    __shared__ float As[2][BK][BM + 4];
    __shared__ float Bs[2][BK][BN + 4];

    const int n0 = blockIdx.x * BN;      // global output column base
    const int m0 = blockIdx.y * BM;      // global output row base
    const int tid = threadIdx.x;
    const int ty = tid >> 4;             // 0..15 -> row micro-tile
    const int tx = tid & 15;             // 0..15 -> col micro-tile

    const float* B = B0;
    int nb = n0;                          // row offset inside selected weight
    if (B1 != nullptr) {
        const int sel = n0 >> 9;          // 0,1,2 (Wq/Wk/Wv); BN=128 never straddles
        B = (sel == 0) ? B0 : ((sel == 1) ? B1 : B2);
        nb = n0 & 511;
    }

    // per-thread load assignment: 2 float4 from A, 2 float4 from B per tile
    const int r0 = tid >> 2;             // 0..63
    const int r1 = (tid + 256) >> 2;     // 64..127
    const int cg0 = (tid & 3) * 4;
    const int cg1 = ((tid + 256) & 3) * 4;

    const float* Abase0 = A + (size_t)(m0 + r0) * lda;
    const float* Abase1 = A + (size_t)(m0 + r1) * lda;
    const float* Bbase0 = B + (size_t)(nb + r0) * 512;
    const float* Bbase1 = B + (size_t)(nb + r1) * 512;

    // accumulators: 8 rows x 4 packed column-pairs
    unsigned long long acc2[8][4];
    #pragma unroll
    for (int i = 0; i < 8; i++)
        #pragma unroll
        for (int j = 0; j < 4; j++) acc2[i][j] = 0ULL;

    // --- preload tile k0=0 into buffer 0 ---
    float4 ra0 = *(const float4*)(Abase0 + cg0);
    float4 ra1 = *(const float4*)(Abase1 + cg1);
    float4 rb0 = *(const float4*)(Bbase0 + cg0);
    float4 rb1 = *(const float4*)(Bbase1 + cg1);
    {
        As[0][cg0 + 0][r0] = ra0.x; As[0][cg0 + 1][r0] = ra0.y;
        As[0][cg0 + 2][r0] = ra0.z; As[0][cg0 + 3][r0] = ra0.w;
        As[0][cg1 + 0][r1] = ra1.x; As[0][cg1 + 1][r1] = ra1.y;
        As[0][cg1 + 2][r1] = ra1.z; As[0][cg1 + 3][r1] = ra1.w;
        Bs[0][cg0 + 0][r0] = rb0.x; Bs[0][cg0 + 1][r0] = rb0.y;
        Bs[0][cg0 + 2][r0] = rb0.z; Bs[0][cg0 + 3][r0] = rb0.w;
        Bs[0][cg1 + 0][r1] = rb1.x; Bs[0][cg1 + 1][r1] = rb1.y;
        Bs[0][cg1 + 2][r1] = rb1.z; Bs[0][cg1 + 3][r1] = rb1.w;
    }
    __syncthreads();

    int buf = 0;
    for (int k0 = 0; k0 < K; k0 += BK) {
        const bool has_next = (k0 + BK) < K;
        // --- issue global prefetch for next tile (overlapped with FMAs) ---
        if (has_next) {
            const int kn = k0 + BK;
            ra0 = *(const float4*)(Abase0 + kn + cg0);
            ra1 = *(const float4*)(Abase1 + kn + cg1);
            rb0 = *(const float4*)(Bbase0 + kn + cg0);
            rb1 = *(const float4*)(Bbase1 + kn + cg1);
        }

        // --- compute current tile, register-double-buffered over kk;
        //     commit prefetched tile to buf^1 after kk==7 (data has landed) ---
        float4 xa0 = *(const float4*)&As[buf][0][ty * 8];
        float4 xa1 = *(const float4*)&As[buf][0][ty * 8 + 4];
        ulonglong2 xb0 = *(const ulonglong2*)&Bs[buf][0][tx * 8];
        ulonglong2 xb1 = *(const ulonglong2*)&Bs[buf][0][tx * 8 + 4];

        #pragma unroll
        for (int kk = 0; kk < BK; kk++) {
            float4 na0, na1;
            ulonglong2 nb0g, nb1g;
            if (kk + 1 < BK) {
                na0  = *(const float4*)&As[buf][kk + 1][ty * 8];
                na1  = *(const float4*)&As[buf][kk + 1][ty * 8 + 4];
                nb0g = *(const ulonglong2*)&Bs[buf][kk + 1][tx * 8];
                nb1g = *(const ulonglong2*)&Bs[buf][kk + 1][tx * 8 + 4];
            }

            const unsigned long long b2[4] = {xb0.x, xb0.y, xb1.x, xb1.y};
            const float a[8] = {xa0.x, xa0.y, xa0.z, xa0.w,
                                xa1.x, xa1.y, xa1.z, xa1.w};
            #pragma unroll
            for (int i = 0; i < 8; i++) {
                const unsigned long long as2 = splat2(a[i]);
                ffma2(acc2[i][0], as2, b2[0], acc2[i][0]);
                ffma2(acc2[i][1], as2, b2[1], acc2[i][1]);
                ffma2(acc2[i][2], as2, b2[2], acc2[i][2]);
                ffma2(acc2[i][3], as2, b2[3], acc2[i][3]);
            }

            // mid-loop smem commit: LDGs from loop head have completed by now;
            // writes go to buf^1 (not read until after the barrier below)
            if (kk == 7) {
                if (has_next) {
                    const int nb2 = buf ^ 1;
                    As[nb2][cg0 + 0][r0] = ra0.x; As[nb2][cg0 + 1][r0] = ra0.y;
                    As[nb2][cg0 + 2][r0] = ra0.z; As[nb2][cg0 + 3][r0] = ra0.w;
                    As[nb2][cg1 + 0][r1] = ra1.x; As[nb2][cg1 + 1][r1] = ra1.y;
                    As[nb2][cg1 + 2][r1] = ra1.z; As[nb2][cg1 + 3][r1] = ra1.w;
                    Bs[nb2][cg0 + 0][r0] = rb0.x; Bs[nb2][cg0 + 1][r0] = rb0.y;
                    Bs[nb2][cg0 + 2][r0] = rb0.z; Bs[nb2][cg0 + 3][r0] = rb0.w;
                    Bs[nb2][cg1 + 0][r1] = rb1.x; Bs[nb2][cg1 + 1][r1] = rb1.y;
                    Bs[nb2][cg1 + 2][r1] = rb1.z; Bs[nb2][cg1 + 3][r1] = rb1.w;
                }
            }

            if (kk + 1 < BK) {
                xa0 = na0; xa1 = na1; xb0 = nb0g; xb1 = nb1g;
            }
        }

        if (has_next) {
            __syncthreads();
            buf ^= 1;
        }
    }

    // --- epilogue: unpack accumulators, optional bias ---
    float accf[8][8];
    #pragma unroll
    for (int i = 0; i < 8; i++)
        #pragma unroll
        for (int j = 0; j < 4; j++)
            unpack2(accf[i][2 * j], accf[i][2 * j + 1], acc2[i][j]);

    if (bias != nullptr) {
        #pragma unroll
        for (int i = 0; i < 8; i++) {
            const size_t crow = (size_t)(m0 + ty * 8 + i) * ldc;
            #pragma unroll
            for (int jv = 0; jv < 2; jv++) {
                const int c = n0 + tx * 8 + jv * 4;
                float4 o;
                o.x = accf[i][jv * 4 + 0] + bias[c + 0];
                o.y = accf[i][jv * 4 + 1] + bias[c + 1];
                o.z = accf[i][jv * 4 + 2] + bias[c + 2];
                o.w = accf[i][jv * 4 + 3] + bias[c + 3];
                *(float4*)(C + crow + c) = o;
            }
        }
    } else {
        #pragma unroll
        for (int i = 0; i < 8; i++) {
            const size_t crow = (size_t)(m0 + ty * 8 + i) * ldc;
            #pragma unroll
            for (int jv = 0; jv < 2; jv++) {
                const int c = n0 + tx * 8 + jv * 4;
                float4 o;
                o.x = accf[i][jv * 4 + 0];
                o.y = accf[i][jv * 4 + 1];
                o.z = accf[i][jv * 4 + 2];
                o.w = accf[i][jv * 4 + 3];
                *(float4*)(C + crow + c) = o;
            }
        }
    }
}

// LIF over time + causal linear attention (elementwise per (m,d)).
// g layout: row (t*16384 + m), cols [0,512)=q, [512,1024)=k, [1024,1536)=v.
__global__ __launch_bounds__(256) void lif_attn(
    const float* __restrict__ g, float* __restrict__ y)
{
    const size_t id = (size_t)blockIdx.x * blockDim.x + threadIdx.x;
    const size_t MD = (size_t)M_PER_T * D_DIM;
    if (id >= MD) return;
    const size_t m = id >> 9;
    const int d = (int)(id & 511);

    float mq = 0.f, mk = 0.f, mv = 0.f, ctx = 0.f;
    #pragma unroll
    for (int t = 0; t < T_STEPS; t++) {
        const size_t r = (size_t)t * M_PER_T + m;
        const float* p = g + r * N_QKV + d;
        const float aq = p[0];
        const float ak = p[512];
        const float av = p[1024];

        mq = 0.9f * mq + aq;
        const float sq = (mq >= 1.0f) ? 1.0f : 0.0f;
        mq -= sq;

        mk = 0.9f * mk + ak;
        const float sk = (mk >= 1.0f) ? 1.0f : 0.0f;
        mk -= sk;

        mv = 0.9f * mv + av;
        const float sv = (mv >= 1.0f) ? 1.0f : 0.0f;
        mv -= sv;

        ctx += sk * sv;                       // cumulative k*v
        y[r * D_DIM + d] = sq * ctx;          // q * context
    }
}

extern "C" void kernel_launch(void* const* d_in, const int* in_sizes, int n_in,
                              void* d_out, int out_size)
{
    (void)in_sizes; (void)n_in; (void)out_size;
    const float* x  = (const float*)d_in[0];
    const float* Wq = (const float*)d_in[1];
    const float* Wk = (const float*)d_in[2];
    const float* Wv = (const float*)d_in[3];
    const float* Wp = (const float*)d_in[4];
    const float* bp = (const float*)d_in[5];
    float* out = (float*)d_out;

    float* pre; cudaGetSymbolAddress((void**)&pre, g_pre);
    float* yb;  cudaGetSymbolAddress((void**)&yb,  g_y);

    // 1) fused QKV projection GEMM: 65536 x 1536 x 512
    {
        dim3 grid(N_QKV / BN, ROWS / BM);
        sgemm_nt<<<grid, 256>>>(x, D_DIM, Wq, Wk, Wv, pre, N_QKV, D_DIM, nullptr);
    }
    // 2) LIF + linear attention elementwise
    {
        const size_t MD = (size_t)M_PER_T * D_DIM;
        lif_attn<<<(unsigned)((MD + 255) / 256), 256>>>(pre, yb);
    }
    // 3) output projection GEMM + bias: 65536 x 512 x 512
    {
        dim3 grid(D_DIM / BN, ROWS / BM);
        sgemm_nt<<<grid, 256>>>(yb, D_DIM, Wp, nullptr, nullptr, out, D_DIM, D_DIM, bp);
    }
}

// round 15
// speedup vs baseline: 1.3100x; 1.3100x over previous
#include <cuda_runtime.h>
#include <cstdint>

// ---------------------------------------------------------------------------
// SpikingSelfAttention: T=4, B=16, N=1024, D=512, H=8 (heads never mix).
//   1) g = x @ [Wq;Wk;Wv]^T          (65536 x 1536 x 512 fp32 GEMM)
//   2) LIF over time + ctx = cumsum_t(k*v), y = q*ctx   (elementwise)
//   3) out = y @ Wp^T + bp           (65536 x 512 x 512 fp32 GEMM)
//
// Numerics contract: per-lane IEEE fp32 FMA, k strictly sequential — bit-
// exact vs reference (rel_err = 0.0 measured).
// R13/R14 lessons: L1TEX/shared crossbar is the saturated resource (95-96%),
// fma caps at ~64%; and regs>128 halves occupancy. This version uses a 16x4
// micro-tile (warp-strip map): A fragments are full-warp broadcast (dedup),
// B fragments are 512B contiguous conflict-free; launch_bounds(256,2) pins
// 2 CTAs/SM.
// ---------------------------------------------------------------------------

#define T_STEPS 4
#define M_PER_T 16384            // B*N
#define ROWS    65536            // T*B*N
#define D_DIM   512
#define N_QKV   1536

// Scratch (allocation-guard-safe: __device__ globals)
__device__ float g_pre[(size_t)ROWS * N_QKV];   // QKV pre-activations, ld=1536
__device__ float g_y[(size_t)ROWS * D_DIM];     // y = q * context,     ld=512

#define BM 128
#define BN 128
#define BK 16

// Packed fp32x2 helpers (sm_103a). f32x2 FMA = 2 independent IEEE fp32 FMAs.
__device__ __forceinline__ void ffma2(unsigned long long& d,
                                      unsigned long long a,
                                      unsigned long long b,
                                      unsigned long long c) {
    asm("fma.rn.f32x2 %0, %1, %2, %3;" : "=l"(d) : "l"(a), "l"(b), "l"(c));
}
__device__ __forceinline__ unsigned long long splat2(float f) {
    unsigned long long d;
    asm("mov.b64 %0, {%1, %1};" : "=l"(d) : "f"(f));
    return d;
}
__device__ __forceinline__ void unpack2(float& lo, float& hi, unsigned long long v) {
    asm("mov.b64 {%0, %1}, %2;" : "=f"(lo), "=f"(hi) : "l"(v));
}

// out[i,j] = sum_k A[i,k] * B[j,k]   (A: M x K row-major, B: N x K row-major)
// If B1 != nullptr, column block selects among {B0,B1,B2} (512 cols each).
// Micro-tile: warp w owns rows [w*16, w*16+16); lane tx owns cols [tx*4, +4).
//   A fragment: 16 floats, identical across the warp -> broadcast LDS.
//   B fragment: 16B/lane, 32 consecutive chunks -> conflict-free LDS.
// acc pairs rows (2p, 2p+1) in one f32x2; a-pairs come packed from smem.
__global__ __launch_bounds__(256, 2) void sgemm_nt(
    const float* __restrict__ A, int lda,
    const float* __restrict__ B0, const float* __restrict__ B1,
    const float* __restrict__ B2,
    float* __restrict__ C, int ldc, int K,
    const float* __restrict__ bias)
{
    __shared__ float As[2][BK][BM + 4];
    __shared__ float Bs[2][BK][BN + 4];

    const int n0 = blockIdx.x * BN;      // global output column base
    const int m0 = blockIdx.y * BM;      // global output row base
    const int tid = threadIdx.x;
    const int wy = tid >> 5;             // 0..7  -> 16-row strip (per warp)
    const int tx = tid & 31;             // 0..31 -> 4-col strip

    const float* B = B0;
    int nb = n0;                          // row offset inside selected weight
    if (B1 != nullptr) {
        const int sel = n0 >> 9;          // 0,1,2 (Wq/Wk/Wv); BN=128 never straddles
        B = (sel == 0) ? B0 : ((sel == 1) ? B1 : B2);
        nb = n0 & 511;
    }

    // per-thread load assignment: 2 float4 from A, 2 float4 from B per tile
    const int r0 = tid >> 2;             // 0..63
    const int r1 = (tid + 256) >> 2;     // 64..127
    const int cg0 = (tid & 3) * 4;
    const int cg1 = ((tid + 256) & 3) * 4;

    const float* Abase0 = A + (size_t)(m0 + r0) * lda;
    const float* Abase1 = A + (size_t)(m0 + r1) * lda;
    const float* Bbase0 = B + (size_t)(nb + r0) * 512;
    const float* Bbase1 = B + (size_t)(nb + r1) * 512;

    // accumulators: 8 row-pairs x 4 columns (each u64 = rows 2p,2p+1 of col j)
    unsigned long long acc2[8][4];
    #pragma unroll
    for (int p = 0; p < 8; p++)
        #pragma unroll
        for (int j = 0; j < 4; j++) acc2[p][j] = 0ULL;

    // --- preload tile k0=0 into buffer 0 ---
    float4 ra0 = *(const float4*)(Abase0 + cg0);
    float4 ra1 = *(const float4*)(Abase1 + cg1);
    float4 rb0 = *(const float4*)(Bbase0 + cg0);
    float4 rb1 = *(const float4*)(Bbase1 + cg1);
    {
        As[0][cg0 + 0][r0] = ra0.x; As[0][cg0 + 1][r0] = ra0.y;
        As[0][cg0 + 2][r0] = ra0.z; As[0][cg0 + 3][r0] = ra0.w;
        As[0][cg1 + 0][r1] = ra1.x; As[0][cg1 + 1][r1] = ra1.y;
        As[0][cg1 + 2][r1] = ra1.z; As[0][cg1 + 3][r1] = ra1.w;
        Bs[0][cg0 + 0][r0] = rb0.x; Bs[0][cg0 + 1][r0] = rb0.y;
        Bs[0][cg0 + 2][r0] = rb0.z; Bs[0][cg0 + 3][r0] = rb0.w;
        Bs[0][cg1 + 0][r1] = rb1.x; Bs[0][cg1 + 1][r1] = rb1.y;
        Bs[0][cg1 + 2][r1] = rb1.z; Bs[0][cg1 + 3][r1] = rb1.w;
    }
    __syncthreads();

    int buf = 0;
    for (int k0 = 0; k0 < K; k0 += BK) {
        const bool has_next = (k0 + BK) < K;
        // --- issue global prefetch for next tile (overlapped with FMAs) ---
        if (has_next) {
            const int kn = k0 + BK;
            ra0 = *(const float4*)(Abase0 + kn + cg0);
            ra1 = *(const float4*)(Abase1 + kn + cg1);
            rb0 = *(const float4*)(Bbase0 + kn + cg0);
            rb1 = *(const float4*)(Bbase1 + kn + cg1);
        }

        // --- compute current tile ---
        #pragma unroll
        for (int kk = 0; kk < BK; kk++) {
            // A fragment: 16 floats = 8 packed row-pairs, broadcast warp-wide
            const ulonglong2 a01 = *(const ulonglong2*)&As[buf][kk][wy * 16];
            const ulonglong2 a23 = *(const ulonglong2*)&As[buf][kk][wy * 16 + 4];
            const ulonglong2 a45 = *(const ulonglong2*)&As[buf][kk][wy * 16 + 8];
            const ulonglong2 a67 = *(const ulonglong2*)&As[buf][kk][wy * 16 + 12];
            // B fragment: 4 floats, 32 consecutive 16B chunks across the warp
            const float4 bf = *(const float4*)&Bs[buf][kk][tx * 4];

            const unsigned long long b0 = splat2(bf.x);
            const unsigned long long b1 = splat2(bf.y);
            const unsigned long long b2 = splat2(bf.z);
            const unsigned long long b3 = splat2(bf.w);

            const unsigned long long ap[8] = {a01.x, a01.y, a23.x, a23.y,
                                              a45.x, a45.y, a67.x, a67.y};
            #pragma unroll
            for (int p = 0; p < 8; p++) {
                ffma2(acc2[p][0], ap[p], b0, acc2[p][0]);
                ffma2(acc2[p][1], ap[p], b1, acc2[p][1]);
                ffma2(acc2[p][2], ap[p], b2, acc2[p][2]);
                ffma2(acc2[p][3], ap[p], b3, acc2[p][3]);
            }
        }

        // --- commit prefetched tile to the other buffer, single barrier ---
        if (has_next) {
            const int nb2 = buf ^ 1;
            As[nb2][cg0 + 0][r0] = ra0.x; As[nb2][cg0 + 1][r0] = ra0.y;
            As[nb2][cg0 + 2][r0] = ra0.z; As[nb2][cg0 + 3][r0] = ra0.w;
            As[nb2][cg1 + 0][r1] = ra1.x; As[nb2][cg1 + 1][r1] = ra1.y;
            As[nb2][cg1 + 2][r1] = ra1.z; As[nb2][cg1 + 3][r1] = ra1.w;
            Bs[nb2][cg0 + 0][r0] = rb0.x; Bs[nb2][cg0 + 1][r0] = rb0.y;
            Bs[nb2][cg0 + 2][r0] = rb0.z; Bs[nb2][cg0 + 3][r0] = rb0.w;
            Bs[nb2][cg1 + 0][r1] = rb1.x; Bs[nb2][cg1 + 1][r1] = rb1.y;
            Bs[nb2][cg1 + 2][r1] = rb1.z; Bs[nb2][cg1 + 3][r1] = rb1.w;
            __syncthreads();
            buf = nb2;
        }
    }

    // --- epilogue: unpack row-pairs, optional bias ---
    float accf[16][4];
    #pragma unroll
    for (int p = 0; p < 8; p++)
        #pragma unroll
        for (int j = 0; j < 4; j++)
            unpack2(accf[2 * p][j], accf[2 * p + 1][j], acc2[p][j]);

    const int c = n0 + tx * 4;
    if (bias != nullptr) {
        const float4 bv = *(const float4*)(bias + c);
        #pragma unroll
        for (int r = 0; r < 16; r++) {
            const size_t crow = (size_t)(m0 + wy * 16 + r) * ldc;
            float4 o;
            o.x = accf[r][0] + bv.x;
            o.y = accf[r][1] + bv.y;
            o.z = accf[r][2] + bv.z;
            o.w = accf[r][3] + bv.w;
            *(float4*)(C + crow + c) = o;
        }
    } else {
        #pragma unroll
        for (int r = 0; r < 16; r++) {
            const size_t crow = (size_t)(m0 + wy * 16 + r) * ldc;
            float4 o;
            o.x = accf[r][0];
            o.y = accf[r][1];
            o.z = accf[r][2];
            o.w = accf[r][3];
            *(float4*)(C + crow + c) = o;
        }
    }
}

// LIF over time + causal linear attention (elementwise per (m,d)).
// g layout: row (t*16384 + m), cols [0,512)=q, [512,1024)=k, [1024,1536)=v.
__global__ __launch_bounds__(256) void lif_attn(
    const float* __restrict__ g, float* __restrict__ y)
{
    const size_t id = (size_t)blockIdx.x * blockDim.x + threadIdx.x;
    const size_t MD = (size_t)M_PER_T * D_DIM;
    if (id >= MD) return;
    const size_t m = id >> 9;
    const int d = (int)(id & 511);

    float mq = 0.f, mk = 0.f, mv = 0.f, ctx = 0.f;
    #pragma unroll
    for (int t = 0; t < T_STEPS; t++) {
        const size_t r = (size_t)t * M_PER_T + m;
        const float* p = g + r * N_QKV + d;
        const float aq = p[0];
        const float ak = p[512];
        const float av = p[1024];

        mq = 0.9f * mq + aq;
        const float sq = (mq >= 1.0f) ? 1.0f : 0.0f;
        mq -= sq;

        mk = 0.9f * mk + ak;
        const float sk = (mk >= 1.0f) ? 1.0f : 0.0f;
        mk -= sk;

        mv = 0.9f * mv + av;
        const float sv = (mv >= 1.0f) ? 1.0f : 0.0f;
        mv -= sv;

        ctx += sk * sv;                       // cumulative k*v
        y[r * D_DIM + d] = sq * ctx;          // q * context
    }
}

extern "C" void kernel_launch(void* const* d_in, const int* in_sizes, int n_in,
                              void* d_out, int out_size)
{
    (void)in_sizes; (void)n_in; (void)out_size;
    const float* x  = (const float*)d_in[0];
    const float* Wq = (const float*)d_in[1];
    const float* Wk = (const float*)d_in[2];
    const float* Wv = (const float*)d_in[3];
    const float* Wp = (const float*)d_in[4];
    const float* bp = (const float*)d_in[5];
    float* out = (float*)d_out;

    float* pre; cudaGetSymbolAddress((void**)&pre, g_pre);
    float* yb;  cudaGetSymbolAddress((void**)&yb,  g_y);

    // 1) fused QKV projection GEMM: 65536 x 1536 x 512
    {
        dim3 grid(N_QKV / BN, ROWS / BM);
        sgemm_nt<<<grid, 256>>>(x, D_DIM, Wq, Wk, Wv, pre, N_QKV, D_DIM, nullptr);
    }
    // 2) LIF + linear attention elementwise
    {
        const size_t MD = (size_t)M_PER_T * D_DIM;
        lif_attn<<<(unsigned)((MD + 255) / 256), 256>>>(pre, yb);
    }
    // 3) output projection GEMM + bias: 65536 x 512 x 512
    {
        dim3 grid(D_DIM / BN, ROWS / BM);
        sgemm_nt<<<grid, 256>>>(yb, D_DIM, Wp, nullptr, nullptr, out, D_DIM, D_DIM, bp);
    }
}